// round 7
// baseline (speedup 1.0000x reference)
#include <cuda_runtime.h>
#include <cuda_bf16.h>

// Problem constants:
//   N events, H=256, W=336, B=8, C=9, HID=100
//   out: [B, 2C, H, W] float32
//   out idx = x + W*y + W*H*i + W*H*C*p01 + 2*W*H*C*b
#define HID        100
#define C_BINS     9
#define W_DIM      336
#define H_DIM      256
#define WH         (W_DIM * H_DIM)          // 86016
#define WHC        (WH * C_BINS)            // 774144
#define WHC2       (2 * WHC)                // 1548288
#define NCELLS     (16 * WH)                // (2b+p01) in [0,16) x pixel
#define CELL_F     12                       // 9 bins + 3 pad, 48 B, 16B-aligned

// LUT over s in [-1,1]: 4097 knots, step 2/4096. Bin shift 0.125 = 256 steps.
#define LUT_SIZE     4097
#define LUT_SCALE    2048.0f
#define BIN_STEP_IDX 256

#define INIT_THREADS 256
#define ENTRIES_PER_BLOCK 64                 // 256 threads / 4 per entry
#define LUT_BLOCKS   65                      // ceil(4097/64)
#define W2T_PITCH    104

__device__ float g_lut[LUT_SIZE];
// Bin-contiguous scratch accumulator. INVARIANT: all-zero at kernel_launch
// entry — zero-initialized at load, and transpose_kernel re-zeroes every cell
// it reads, restoring the invariant at the end of every launch/replay.
__device__ float g_scratch[(size_t)NCELLS * CELL_F];   // 66 MB

__device__ __forceinline__ float leaky(float v) {
    return v >= 0.0f ? v : 0.1f * v;
}

// LUT build only: 4 threads cooperate per entry.
__global__ void __launch_bounds__(INIT_THREADS)
lut_kernel(const float* __restrict__ w1, const float* __restrict__ b1,
           const float* __restrict__ w2, const float* __restrict__ b2,
           const float* __restrict__ w3, const float* __restrict__ b3) {
    __shared__ float s_w2t[HID * W2T_PITCH];
    __shared__ float s_w1[HID], s_b1[HID], s_b2[HID], s_w3[HID];

    int tid = threadIdx.x;
    for (int i = tid; i < HID * HID; i += INIT_THREADS) {
        int k = i / HID, j = i % HID;          // w2 is [k][j]
        s_w2t[j * W2T_PITCH + k] = w2[i];
    }
    if (tid < HID) {
        s_w1[tid] = w1[tid];
        s_b1[tid] = b1[tid];
        s_b2[tid] = b2[tid];
        s_w3[tid] = w3[tid];
    }
    __syncthreads();

    int entry = blockIdx.x * ENTRIES_PER_BLOCK + (tid >> 2);
    if (entry > LUT_SIZE - 1) entry = LUT_SIZE - 1;
    int q = tid & 3;

    float s = -1.0f + (float)entry * (2.0f / 4096.0f);

    float h1[HID];
#pragma unroll
    for (int k = 0; k < HID; ++k)
        h1[k] = leaky(fmaf(s, s_w1[k], s_b1[k]));

    float acc = 0.0f;
    int j0 = q * 25;
#pragma unroll 1
    for (int jj = 0; jj < 25; ++jj) {
        int j = j0 + jj;
        float a = s_b2[j];
        const float4* row = reinterpret_cast<const float4*>(&s_w2t[j * W2T_PITCH]);
#pragma unroll
        for (int k4 = 0; k4 < 25; ++k4) {
            float4 w = row[k4];
            a = fmaf(h1[4 * k4 + 0], w.x, a);
            a = fmaf(h1[4 * k4 + 1], w.y, a);
            a = fmaf(h1[4 * k4 + 2], w.z, a);
            a = fmaf(h1[4 * k4 + 3], w.w, a);
        }
        acc = fmaf(s_w3[j], leaky(a), acc);
    }

    acc += __shfl_xor_sync(0xffffffffu, acc, 1);
    acc += __shfl_xor_sync(0xffffffffu, acc, 2);
    if (q == 0)
        g_lut[entry] = acc + __ldg(b3);
}

// Scatter into bin-contiguous scratch using vector reductions:
// 9 bins -> red.v4 + red.v4 + red.f32 (3 L2 ops instead of 9).
__global__ void __launch_bounds__(256)
scatter_kernel(const float* __restrict__ ev, int N) {
    int n = blockIdx.x * blockDim.x + threadIdx.x;
    if (n >= N) return;

    const float* e = ev + 5ll * n;
    float xf = __ldg(e + 0), yf = __ldg(e + 1), t = __ldg(e + 2);
    float pf = __ldg(e + 3), bf = __ldg(e + 4);

    int p01  = (pf > 0.0f) ? 1 : 0;
    int cell = ((int)bf * 2 + p01) * WH + (int)xf + W_DIM * (int)yf;
    float* cp = g_scratch + (size_t)cell * CELL_F;

    float u0 = fmaf(t, LUT_SCALE, LUT_SCALE);
    int   i0 = (int)u0;
    if (i0 > LUT_SIZE - 2) i0 = LUT_SIZE - 2;
    float fr = u0 - (float)i0;

    float v[C_BINS];
#pragma unroll
    for (int i = 0; i < C_BINS; ++i) {
        int base = i0 - BIN_STEP_IDX * i;
        float v0 = g_lut[base];
        float v1 = g_lut[base + 1];
        v[i] = t * fmaf(fr, v1 - v0, v0);
    }

    asm volatile("red.global.add.v4.f32 [%0], {%1,%2,%3,%4};"
                 :: "l"(cp), "f"(v[0]), "f"(v[1]), "f"(v[2]), "f"(v[3])
                 : "memory");
    asm volatile("red.global.add.v4.f32 [%0], {%1,%2,%3,%4};"
                 :: "l"(cp + 4), "f"(v[4]), "f"(v[5]), "f"(v[6]), "f"(v[7])
                 : "memory");
    atomicAdd(cp + 8, v[8]);
}

// Transpose scratch -> reference output layout, then re-zero the scratch
// cell (restores the all-zero invariant for the next launch/replay).
__global__ void __launch_bounds__(256)
transpose_kernel(float* __restrict__ out) {
    int c = blockIdx.x * blockDim.x + threadIdx.x;
    if (c >= NCELLS) return;

    int q  = c % WH;
    int pb = c / WH;                 // 2*b + p01
    float4* s4 = reinterpret_cast<float4*>(g_scratch + (size_t)c * CELL_F);
    float4 a = s4[0];
    float4 b = s4[1];
    float  v8 = s4[2].x;

    const float4 z = make_float4(0.f, 0.f, 0.f, 0.f);
    s4[0] = z;
    s4[1] = z;
    s4[2] = z;

    float* o = out + q + (pb & 1) * WHC + (pb >> 1) * WHC2;
    o[0 * WH] = a.x;  o[1 * WH] = a.y;  o[2 * WH] = a.z;  o[3 * WH] = a.w;
    o[4 * WH] = b.x;  o[5 * WH] = b.y;  o[6 * WH] = b.z;  o[7 * WH] = b.w;
    o[8 * WH] = v8;
}

extern "C" void kernel_launch(void* const* d_in, const int* in_sizes, int n_in,
                              void* d_out, int out_size) {
    // events = largest input; weights matched by size in declared order.
    int ie = 0;
    for (int i = 1; i < n_in; ++i)
        if (in_sizes[i] > in_sizes[ie]) ie = i;

    const int want[6] = {100, 100, 10000, 100, 100, 1};
    const float* wp[6] = {nullptr, nullptr, nullptr, nullptr, nullptr, nullptr};
    int wi = 0;
    for (int i = 0; i < n_in && wi < 6; ++i) {
        if (i == ie) continue;
        if (in_sizes[i] == want[wi])
            wp[wi++] = (const float*)d_in[i];
    }

    const float* events = (const float*)d_in[ie];
    int N = in_sizes[ie] / 5;
    float* out = (float*)d_out;

    lut_kernel<<<LUT_BLOCKS, INIT_THREADS>>>(
        wp[0], wp[1], wp[2], wp[3], wp[4], wp[5]);

    int blocks = (N + 255) / 256;
    scatter_kernel<<<blocks, 256>>>(events, N);

    int tblocks = (NCELLS + 255) / 256;
    transpose_kernel<<<tblocks, 256>>>(out);
}

// round 8
// speedup vs baseline: 1.5229x; 1.5229x over previous
#include <cuda_runtime.h>
#include <cuda_bf16.h>

// Problem constants:
//   N events, H=256, W=336, B=8, C=9, HID=100
//   out: [B, 2C, H, W] float32
//   out idx = x + W*y + W*H*i + W*H*C*p01 + 2*W*H*C*b
#define HID        100
#define C_BINS     9
#define W_DIM      336
#define H_DIM      256
#define WH         (W_DIM * H_DIM)          // 86016
#define WHC        (WH * C_BINS)            // 774144
#define WHC2       (2 * WHC)                // 1548288
#define NCELLS     (16 * WH)                // (2b+p01) in [0,16) x pixel
#define CELL_F     12                       // 9 bins + 3 pad, 48 B, 16B-aligned

// LUT over s in [-1,1]: 4097 knots, step 2/4096. Bin shift 0.125 = 256 steps.
#define LUT_SIZE     4097
#define LUT_SCALE    2048.0f
#define BIN_STEP_IDX 256

#define INIT_THREADS 256
#define LUT_BLOCKS   513                     // 513 blocks * 8 warps = 4104 >= 4097
#define ZERO_BLOCKS  3072

__device__ float g_lut[LUT_SIZE];
__device__ float g_scratch[(size_t)NCELLS * CELL_F];   // 66 MB, bin-contiguous

__device__ __forceinline__ float leaky(float v) {
    return v >= 0.0f ? v : 0.1f * v;
}

// Fused init:
//  - blocks [0, LUT_BLOCKS): warp-cooperative LUT build (one warp per entry,
//    no smem, low regs — keeps kernel-wide occupancy high)
//  - blocks [LUT_BLOCKS, ...): zero scratch (also warms L2 for the scatter)
__global__ void __launch_bounds__(INIT_THREADS)
init_kernel(const float* __restrict__ w1, const float* __restrict__ b1,
            const float* __restrict__ w2, const float* __restrict__ b2,
            const float* __restrict__ w3, const float* __restrict__ b3) {
    if (blockIdx.x >= LUT_BLOCKS) {
        float4* s4 = reinterpret_cast<float4*>(g_scratch);
        const int n4 = NCELLS * CELL_F / 4;
        const float4 z = make_float4(0.f, 0.f, 0.f, 0.f);
        int zb = blockIdx.x - LUT_BLOCKS;
        int stride = (gridDim.x - LUT_BLOCKS) * INIT_THREADS;
        for (int k = zb * INIT_THREADS + threadIdx.x; k < n4; k += stride)
            s4[k] = z;
        return;
    }

    // ---- LUT role: one warp per entry ----
    const int lane = threadIdx.x & 31;
    int entry = blockIdx.x * 8 + (threadIdx.x >> 5);
    if (entry > LUT_SIZE - 1) entry = LUT_SIZE - 1;   // dup work, same value

    const float s = -1.0f + (float)entry * (2.0f / 4096.0f);

    // h1 striped across lanes: lane holds k = lane, lane+32, lane+64, lane+96
    float hk0 = leaky(fmaf(s, __ldg(w1 + lane),      __ldg(b1 + lane)));
    float hk1 = leaky(fmaf(s, __ldg(w1 + lane + 32), __ldg(b1 + lane + 32)));
    float hk2 = leaky(fmaf(s, __ldg(w1 + lane + 64), __ldg(b1 + lane + 64)));
    float hk3 = (lane < 4)
              ? leaky(fmaf(s, __ldg(w1 + lane + 96), __ldg(b1 + lane + 96)))
              : 0.0f;

    // Each lane accumulates 4 output columns j = 4*jl .. 4*jl+3
    const int jl = (lane < 25) ? lane : 24;           // lanes 25-31 dup lane 24
    float4 a = __ldg((const float4*)b2 + jl);

    const float4* w2v = (const float4*)w2;            // w2[k][j], row = 25 float4
#pragma unroll
    for (int k = 0; k < HID; ++k) {
        float hpart = (k < 32) ? hk0 : (k < 64) ? hk1 : (k < 96) ? hk2 : hk3;
        float h = __shfl_sync(0xffffffffu, hpart, k & 31);
        float4 w = __ldg(w2v + k * 25 + jl);
        a.x = fmaf(h, w.x, a.x);
        a.y = fmaf(h, w.y, a.y);
        a.z = fmaf(h, w.z, a.z);
        a.w = fmaf(h, w.w, a.w);
    }

    float acc = 0.0f;
    if (lane < 25) {
        float4 w3v = __ldg((const float4*)w3 + jl);
        acc  = w3v.x * leaky(a.x);
        acc += w3v.y * leaky(a.y);
        acc += w3v.z * leaky(a.z);
        acc += w3v.w * leaky(a.w);
    }
    acc += __shfl_xor_sync(0xffffffffu, acc, 16);
    acc += __shfl_xor_sync(0xffffffffu, acc, 8);
    acc += __shfl_xor_sync(0xffffffffu, acc, 4);
    acc += __shfl_xor_sync(0xffffffffu, acc, 2);
    acc += __shfl_xor_sync(0xffffffffu, acc, 1);
    if (lane == 0)
        g_lut[entry] = acc + __ldg(b3);
}

// Scatter into bin-contiguous scratch using vector reductions:
// 9 bins -> red.v4 + red.v4 + red.f32 (3 L2 ops instead of 9).
__global__ void __launch_bounds__(256)
scatter_kernel(const float* __restrict__ ev, int N) {
    int n = blockIdx.x * blockDim.x + threadIdx.x;
    if (n >= N) return;

    const float* e = ev + 5ll * n;
    float xf = __ldg(e + 0), yf = __ldg(e + 1), t = __ldg(e + 2);
    float pf = __ldg(e + 3), bf = __ldg(e + 4);

    int p01  = (pf > 0.0f) ? 1 : 0;
    int cell = ((int)bf * 2 + p01) * WH + (int)xf + W_DIM * (int)yf;
    float* cp = g_scratch + (size_t)cell * CELL_F;

    float u0 = fmaf(t, LUT_SCALE, LUT_SCALE);
    int   i0 = (int)u0;
    if (i0 > LUT_SIZE - 2) i0 = LUT_SIZE - 2;
    float fr = u0 - (float)i0;

    float v[C_BINS];
#pragma unroll
    for (int i = 0; i < C_BINS; ++i) {
        int base = i0 - BIN_STEP_IDX * i;
        float v0 = g_lut[base];
        float v1 = g_lut[base + 1];
        v[i] = t * fmaf(fr, v1 - v0, v0);
    }

    asm volatile("red.global.add.v4.f32 [%0], {%1,%2,%3,%4};"
                 :: "l"(cp), "f"(v[0]), "f"(v[1]), "f"(v[2]), "f"(v[3])
                 : "memory");
    asm volatile("red.global.add.v4.f32 [%0], {%1,%2,%3,%4};"
                 :: "l"(cp + 4), "f"(v[4]), "f"(v[5]), "f"(v[6]), "f"(v[7])
                 : "memory");
    atomicAdd(cp + 8, v[8]);
}

// Transpose scratch -> reference output layout.
__global__ void __launch_bounds__(256)
transpose_kernel(float* __restrict__ out) {
    int c = blockIdx.x * blockDim.x + threadIdx.x;
    if (c >= NCELLS) return;

    int q  = c % WH;
    int pb = c / WH;                 // 2*b + p01
    const float4* s4 = reinterpret_cast<const float4*>(g_scratch + (size_t)c * CELL_F);
    float4 a = __ldg(s4 + 0);
    float4 b = __ldg(s4 + 1);
    float  v8 = __ldg(s4 + 2).x;

    float* o = out + q + (pb & 1) * WHC + (pb >> 1) * WHC2;
    o[0 * WH] = a.x;  o[1 * WH] = a.y;  o[2 * WH] = a.z;  o[3 * WH] = a.w;
    o[4 * WH] = b.x;  o[5 * WH] = b.y;  o[6 * WH] = b.z;  o[7 * WH] = b.w;
    o[8 * WH] = v8;
}

extern "C" void kernel_launch(void* const* d_in, const int* in_sizes, int n_in,
                              void* d_out, int out_size) {
    // events = largest input; weights matched by size in declared order.
    int ie = 0;
    for (int i = 1; i < n_in; ++i)
        if (in_sizes[i] > in_sizes[ie]) ie = i;

    const int want[6] = {100, 100, 10000, 100, 100, 1};
    const float* wp[6] = {nullptr, nullptr, nullptr, nullptr, nullptr, nullptr};
    int wi = 0;
    for (int i = 0; i < n_in && wi < 6; ++i) {
        if (i == ie) continue;
        if (in_sizes[i] == want[wi])
            wp[wi++] = (const float*)d_in[i];
    }

    const float* events = (const float*)d_in[ie];
    int N = in_sizes[ie] / 5;
    float* out = (float*)d_out;

    init_kernel<<<LUT_BLOCKS + ZERO_BLOCKS, INIT_THREADS>>>(
        wp[0], wp[1], wp[2], wp[3], wp[4], wp[5]);

    int blocks = (N + 255) / 256;
    scatter_kernel<<<blocks, 256>>>(events, N);

    int tblocks = (NCELLS + 255) / 256;
    transpose_kernel<<<tblocks, 256>>>(out);
}

// round 9
// speedup vs baseline: 1.5835x; 1.0398x over previous
#include <cuda_runtime.h>
#include <cuda_bf16.h>

// Problem constants:
//   N events, H=256, W=336, B=8, C=9, HID=100
//   out: [B, 2C, H, W] float32
//   out idx = x + W*y + W*H*i + W*H*C*p01 + 2*W*H*C*b
#define HID        100
#define C_BINS     9
#define W_DIM      336
#define H_DIM      256
#define WH         (W_DIM * H_DIM)          // 86016
#define WHC        (WH * C_BINS)            // 774144
#define WHC2       (2 * WHC)                // 1548288
#define NCELLS     (16 * WH)                // (2b+p01) in [0,16) x pixel

// LUT over s in [-1,1]: 4097 knots, step 2/4096. Bin shift 0.125 = 256 steps.
#define LUT_SIZE     4097
#define LUT_SCALE    2048.0f
#define BIN_STEP_IDX 256

#define INIT_THREADS 256
#define LUT_BLOCKS   513                     // 513 * 8 warps = 4104 >= 4097
#define ZERO_BLOCKS  1184                    // 148 SMs * 8 — one persistent wave

// SoA scratch: bins 0-3, 4-7 as float4 streams, bin 8 scalar. 36 B/cell.
__device__ float4 g_sA[NCELLS];              // 22 MB
__device__ float4 g_sB[NCELLS];              // 22 MB
__device__ float  g_sS[NCELLS];              // 5.5 MB
__device__ float  g_lut[LUT_SIZE];

__device__ __forceinline__ float leaky(float v) {
    return v >= 0.0f ? v : 0.1f * v;
}

// Fused init:
//  - blocks [0, LUT_BLOCKS): warp-cooperative LUT build (one warp per entry)
//  - blocks [LUT_BLOCKS, ...): zero SoA scratch (also warms L2 for scatter)
__global__ void __launch_bounds__(INIT_THREADS)
init_kernel(const float* __restrict__ w1, const float* __restrict__ b1,
            const float* __restrict__ w2, const float* __restrict__ b2,
            const float* __restrict__ w3, const float* __restrict__ b3) {
    if (blockIdx.x >= LUT_BLOCKS) {
        const float4 z = make_float4(0.f, 0.f, 0.f, 0.f);
        int zb = blockIdx.x - LUT_BLOCKS;
        int stride = ZERO_BLOCKS * INIT_THREADS;
        int tid0 = zb * INIT_THREADS + threadIdx.x;
        for (int k = tid0; k < NCELLS; k += stride) {
            g_sA[k] = z;
            g_sB[k] = z;
        }
        float4* s4 = reinterpret_cast<float4*>(g_sS);
        for (int k = tid0; k < NCELLS / 4; k += stride)
            s4[k] = z;
        return;
    }

    // ---- LUT role: one warp per entry ----
    const int lane = threadIdx.x & 31;
    int entry = blockIdx.x * 8 + (threadIdx.x >> 5);
    if (entry > LUT_SIZE - 1) entry = LUT_SIZE - 1;   // dup work, same value

    const float s = -1.0f + (float)entry * (2.0f / 4096.0f);

    // h1 striped across lanes: lane holds k = lane, lane+32, lane+64, lane+96
    float hk0 = leaky(fmaf(s, __ldg(w1 + lane),      __ldg(b1 + lane)));
    float hk1 = leaky(fmaf(s, __ldg(w1 + lane + 32), __ldg(b1 + lane + 32)));
    float hk2 = leaky(fmaf(s, __ldg(w1 + lane + 64), __ldg(b1 + lane + 64)));
    float hk3 = (lane < 4)
              ? leaky(fmaf(s, __ldg(w1 + lane + 96), __ldg(b1 + lane + 96)))
              : 0.0f;

    // Each lane accumulates 4 output columns j = 4*jl .. 4*jl+3
    const int jl = (lane < 25) ? lane : 24;           // lanes 25-31 dup lane 24
    float4 a = __ldg((const float4*)b2 + jl);

    const float4* w2v = (const float4*)w2;            // w2[k][j], row = 25 float4
#pragma unroll
    for (int k = 0; k < HID; ++k) {
        float hpart = (k < 32) ? hk0 : (k < 64) ? hk1 : (k < 96) ? hk2 : hk3;
        float h = __shfl_sync(0xffffffffu, hpart, k & 31);
        float4 w = __ldg(w2v + k * 25 + jl);
        a.x = fmaf(h, w.x, a.x);
        a.y = fmaf(h, w.y, a.y);
        a.z = fmaf(h, w.z, a.z);
        a.w = fmaf(h, w.w, a.w);
    }

    float acc = 0.0f;
    if (lane < 25) {
        float4 w3v = __ldg((const float4*)w3 + jl);
        acc  = w3v.x * leaky(a.x);
        acc += w3v.y * leaky(a.y);
        acc += w3v.z * leaky(a.z);
        acc += w3v.w * leaky(a.w);
    }
    acc += __shfl_xor_sync(0xffffffffu, acc, 16);
    acc += __shfl_xor_sync(0xffffffffu, acc, 8);
    acc += __shfl_xor_sync(0xffffffffu, acc, 4);
    acc += __shfl_xor_sync(0xffffffffu, acc, 2);
    acc += __shfl_xor_sync(0xffffffffu, acc, 1);
    if (lane == 0)
        g_lut[entry] = acc + __ldg(b3);
}

// Scatter into SoA scratch: red.v4 (bins 0-3) + red.v4 (bins 4-7) + red (bin 8).
__global__ void __launch_bounds__(256)
scatter_kernel(const float* __restrict__ ev, int N) {
    int n = blockIdx.x * blockDim.x + threadIdx.x;
    if (n >= N) return;

    const float* e = ev + 5ll * n;
    float xf = __ldg(e + 0), yf = __ldg(e + 1), t = __ldg(e + 2);
    float pf = __ldg(e + 3), bf = __ldg(e + 4);

    int p01  = (pf > 0.0f) ? 1 : 0;
    int cell = ((int)bf * 2 + p01) * WH + (int)xf + W_DIM * (int)yf;

    float u0 = fmaf(t, LUT_SCALE, LUT_SCALE);
    int   i0 = (int)u0;
    if (i0 > LUT_SIZE - 2) i0 = LUT_SIZE - 2;
    float fr = u0 - (float)i0;

    float v[C_BINS];
#pragma unroll
    for (int i = 0; i < C_BINS; ++i) {
        int base = i0 - BIN_STEP_IDX * i;
        float v0 = g_lut[base];
        float v1 = g_lut[base + 1];
        v[i] = t * fmaf(fr, v1 - v0, v0);
    }

    asm volatile("red.global.add.v4.f32 [%0], {%1,%2,%3,%4};"
                 :: "l"(g_sA + cell), "f"(v[0]), "f"(v[1]), "f"(v[2]), "f"(v[3])
                 : "memory");
    asm volatile("red.global.add.v4.f32 [%0], {%1,%2,%3,%4};"
                 :: "l"(g_sB + cell), "f"(v[4]), "f"(v[5]), "f"(v[6]), "f"(v[7])
                 : "memory");
    atomicAdd(g_sS + cell, v[8]);
}

// Transpose SoA scratch -> reference output layout. All loads coalesced
// float4/float streams; stores coalesced per-bin 128B wavefronts.
__global__ void __launch_bounds__(256)
transpose_kernel(float* __restrict__ out) {
    int c = blockIdx.x * blockDim.x + threadIdx.x;
    if (c >= NCELLS) return;

    int q  = c % WH;
    int pb = c / WH;                 // 2*b + p01
    float4 a = __ldg(g_sA + c);
    float4 b = __ldg(g_sB + c);
    float  v8 = __ldg(g_sS + c);

    float* o = out + q + (pb & 1) * WHC + (pb >> 1) * WHC2;
    o[0 * WH] = a.x;  o[1 * WH] = a.y;  o[2 * WH] = a.z;  o[3 * WH] = a.w;
    o[4 * WH] = b.x;  o[5 * WH] = b.y;  o[6 * WH] = b.z;  o[7 * WH] = b.w;
    o[8 * WH] = v8;
}

extern "C" void kernel_launch(void* const* d_in, const int* in_sizes, int n_in,
                              void* d_out, int out_size) {
    // events = largest input; weights matched by size in declared order.
    int ie = 0;
    for (int i = 1; i < n_in; ++i)
        if (in_sizes[i] > in_sizes[ie]) ie = i;

    const int want[6] = {100, 100, 10000, 100, 100, 1};
    const float* wp[6] = {nullptr, nullptr, nullptr, nullptr, nullptr, nullptr};
    int wi = 0;
    for (int i = 0; i < n_in && wi < 6; ++i) {
        if (i == ie) continue;
        if (in_sizes[i] == want[wi])
            wp[wi++] = (const float*)d_in[i];
    }

    const float* events = (const float*)d_in[ie];
    int N = in_sizes[ie] / 5;
    float* out = (float*)d_out;

    init_kernel<<<LUT_BLOCKS + ZERO_BLOCKS, INIT_THREADS>>>(
        wp[0], wp[1], wp[2], wp[3], wp[4], wp[5]);

    int blocks = (N + 255) / 256;
    scatter_kernel<<<blocks, 256>>>(events, N);

    int tblocks = (NCELLS + 255) / 256;
    transpose_kernel<<<tblocks, 256>>>(out);
}

// round 10
// speedup vs baseline: 1.8763x; 1.1849x over previous
#include <cuda_runtime.h>
#include <cuda_bf16.h>

// Problem constants:
//   N events, H=256, W=336, B=8, C=9, HID=100
//   out: [B, 2C, H, W] float32
//   out idx = x + W*y + W*H*i + W*H*C*p01 + 2*W*H*C*b
#define HID        100
#define C_BINS     9
#define W_DIM      336
#define H_DIM      256
#define WH         (W_DIM * H_DIM)          // 86016
#define WHC        (WH * C_BINS)            // 774144
#define WHC2       (2 * WHC)                // 1548288
#define NCELLS     (16 * WH)                // (2b+p01) in [0,16) x pixel

// LUT over s in [-1,1]: 1025 knots, step 2/1024. Bin shift 0.125 = 64 steps.
#define LUT_SIZE     1025
#define LUT_SCALE    512.0f
#define BIN_STEP_IDX 64

#define INIT_THREADS 256
#define LUT_BLOCKS   129                     // 129 * 8 warps = 1032 >= 1025
#define ZERO_BLOCKS  1184                    // 148 SMs * 8 — one persistent wave

// SoA scratch: bins 0-3, 4-7 as float4 streams, bin 8 scalar. 36 B/cell.
__device__ float4 g_sA[NCELLS];              // 22 MB
__device__ float4 g_sB[NCELLS];              // 22 MB
__device__ float  g_sS[NCELLS];              // 5.5 MB
__device__ float  g_lut[LUT_SIZE];

__device__ __forceinline__ float leaky(float v) {
    return v >= 0.0f ? v : 0.1f * v;
}

// Fused init:
//  - blocks [0, LUT_BLOCKS): warp-cooperative LUT build (one warp per entry)
//  - blocks [LUT_BLOCKS, ...): zero SoA scratch (also warms L2 for scatter)
__global__ void __launch_bounds__(INIT_THREADS)
init_kernel(const float* __restrict__ w1, const float* __restrict__ b1,
            const float* __restrict__ w2, const float* __restrict__ b2,
            const float* __restrict__ w3, const float* __restrict__ b3) {
    if (blockIdx.x >= LUT_BLOCKS) {
        const float4 z = make_float4(0.f, 0.f, 0.f, 0.f);
        int zb = blockIdx.x - LUT_BLOCKS;
        int stride = ZERO_BLOCKS * INIT_THREADS;
        int tid0 = zb * INIT_THREADS + threadIdx.x;
        for (int k = tid0; k < NCELLS; k += stride) {
            g_sA[k] = z;
            g_sB[k] = z;
        }
        float4* s4 = reinterpret_cast<float4*>(g_sS);
        for (int k = tid0; k < NCELLS / 4; k += stride)
            s4[k] = z;
        return;
    }

    // ---- LUT role: one warp per entry ----
    const int lane = threadIdx.x & 31;
    int entry = blockIdx.x * 8 + (threadIdx.x >> 5);
    if (entry > LUT_SIZE - 1) entry = LUT_SIZE - 1;   // dup work, same value

    const float s = -1.0f + (float)entry * (2.0f / 1024.0f);

    // h1 striped across lanes: lane holds k = lane, lane+32, lane+64, lane+96
    float hk0 = leaky(fmaf(s, __ldg(w1 + lane),      __ldg(b1 + lane)));
    float hk1 = leaky(fmaf(s, __ldg(w1 + lane + 32), __ldg(b1 + lane + 32)));
    float hk2 = leaky(fmaf(s, __ldg(w1 + lane + 64), __ldg(b1 + lane + 64)));
    float hk3 = (lane < 4)
              ? leaky(fmaf(s, __ldg(w1 + lane + 96), __ldg(b1 + lane + 96)))
              : 0.0f;

    // Each lane accumulates 4 output columns j = 4*jl .. 4*jl+3
    const int jl = (lane < 25) ? lane : 24;           // lanes 25-31 dup lane 24
    float4 a = __ldg((const float4*)b2 + jl);

    const float4* w2v = (const float4*)w2;            // w2[k][j], row = 25 float4
#pragma unroll
    for (int k = 0; k < HID; ++k) {
        float hpart = (k < 32) ? hk0 : (k < 64) ? hk1 : (k < 96) ? hk2 : hk3;
        float h = __shfl_sync(0xffffffffu, hpart, k & 31);
        float4 w = __ldg(w2v + k * 25 + jl);
        a.x = fmaf(h, w.x, a.x);
        a.y = fmaf(h, w.y, a.y);
        a.z = fmaf(h, w.z, a.z);
        a.w = fmaf(h, w.w, a.w);
    }

    float acc = 0.0f;
    if (lane < 25) {
        float4 w3v = __ldg((const float4*)w3 + jl);
        acc  = w3v.x * leaky(a.x);
        acc += w3v.y * leaky(a.y);
        acc += w3v.z * leaky(a.z);
        acc += w3v.w * leaky(a.w);
    }
    acc += __shfl_xor_sync(0xffffffffu, acc, 16);
    acc += __shfl_xor_sync(0xffffffffu, acc, 8);
    acc += __shfl_xor_sync(0xffffffffu, acc, 4);
    acc += __shfl_xor_sync(0xffffffffu, acc, 2);
    acc += __shfl_xor_sync(0xffffffffu, acc, 1);
    if (lane == 0)
        g_lut[entry] = acc + __ldg(b3);
}

// Scatter into SoA scratch: red.v4 (bins 0-3) + red.v4 (bins 4-7) + red (bin 8).
__global__ void __launch_bounds__(256)
scatter_kernel(const float* __restrict__ ev, int N) {
    int n = blockIdx.x * blockDim.x + threadIdx.x;
    if (n >= N) return;

    const float* e = ev + 5ll * n;
    float xf = __ldg(e + 0), yf = __ldg(e + 1), t = __ldg(e + 2);
    float pf = __ldg(e + 3), bf = __ldg(e + 4);

    int p01  = (pf > 0.0f) ? 1 : 0;
    int cell = ((int)bf * 2 + p01) * WH + (int)xf + W_DIM * (int)yf;

    float u0 = fmaf(t, LUT_SCALE, LUT_SCALE);
    int   i0 = (int)u0;
    if (i0 > LUT_SIZE - 2) i0 = LUT_SIZE - 2;
    float fr = u0 - (float)i0;

    float v[C_BINS];
#pragma unroll
    for (int i = 0; i < C_BINS; ++i) {
        int base = i0 - BIN_STEP_IDX * i;
        float v0 = g_lut[base];
        float v1 = g_lut[base + 1];
        v[i] = t * fmaf(fr, v1 - v0, v0);
    }

    asm volatile("red.global.add.v4.f32 [%0], {%1,%2,%3,%4};"
                 :: "l"(g_sA + cell), "f"(v[0]), "f"(v[1]), "f"(v[2]), "f"(v[3])
                 : "memory");
    asm volatile("red.global.add.v4.f32 [%0], {%1,%2,%3,%4};"
                 :: "l"(g_sB + cell), "f"(v[4]), "f"(v[5]), "f"(v[6]), "f"(v[7])
                 : "memory");
    atomicAdd(g_sS + cell, v[8]);
}

// Transpose SoA scratch -> reference output layout. All loads coalesced
// float4/float streams; stores coalesced per-bin 128B wavefronts.
__global__ void __launch_bounds__(256)
transpose_kernel(float* __restrict__ out) {
    int c = blockIdx.x * blockDim.x + threadIdx.x;
    if (c >= NCELLS) return;

    int q  = c % WH;
    int pb = c / WH;                 // 2*b + p01
    float4 a = __ldg(g_sA + c);
    float4 b = __ldg(g_sB + c);
    float  v8 = __ldg(g_sS + c);

    float* o = out + q + (pb & 1) * WHC + (pb >> 1) * WHC2;
    o[0 * WH] = a.x;  o[1 * WH] = a.y;  o[2 * WH] = a.z;  o[3 * WH] = a.w;
    o[4 * WH] = b.x;  o[5 * WH] = b.y;  o[6 * WH] = b.z;  o[7 * WH] = b.w;
    o[8 * WH] = v8;
}

extern "C" void kernel_launch(void* const* d_in, const int* in_sizes, int n_in,
                              void* d_out, int out_size) {
    // events = largest input; weights matched by size in declared order.
    int ie = 0;
    for (int i = 1; i < n_in; ++i)
        if (in_sizes[i] > in_sizes[ie]) ie = i;

    const int want[6] = {100, 100, 10000, 100, 100, 1};
    const float* wp[6] = {nullptr, nullptr, nullptr, nullptr, nullptr, nullptr};
    int wi = 0;
    for (int i = 0; i < n_in && wi < 6; ++i) {
        if (i == ie) continue;
        if (in_sizes[i] == want[wi])
            wp[wi++] = (const float*)d_in[i];
    }

    const float* events = (const float*)d_in[ie];
    int N = in_sizes[ie] / 5;
    float* out = (float*)d_out;

    init_kernel<<<LUT_BLOCKS + ZERO_BLOCKS, INIT_THREADS>>>(
        wp[0], wp[1], wp[2], wp[3], wp[4], wp[5]);

    int blocks = (N + 255) / 256;
    scatter_kernel<<<blocks, 256>>>(events, N);

    int tblocks = (NCELLS + 255) / 256;
    transpose_kernel<<<tblocks, 256>>>(out);
}